// round 9
// baseline (speedup 1.0000x reference)
#include <cuda_runtime.h>
#include <cuda_bf16.h>
#include <cstdint>
#include <math.h>

// ===========================================================================
#define T_TOK   65536
#define NWIN    4096
#define NPIX    4096

// scratch (device globals)
__device__ float g_X  [T_TOK * 128];
__device__ float g_QKV[T_TOK * 384];
__device__ float g_Hid[(size_t)T_TOK * 512];   // NHWC x / mlp hidden
__device__ float g_Xr [T_TOK * 128];
__device__ float g_h  [NPIX * 128];
__device__ float g_c  [NPIX * 128];
__device__ float g_gates[NPIX * 512];
__device__ float g_Wc [128 * 512];
__device__ float g_Wl [512 * 256];

__device__ __forceinline__ uint32_t f2tf32(float f) {
    uint32_t u; asm("cvt.rna.tf32.f32 %0, %1;" : "=r"(u) : "f"(f)); return u;
}
__device__ __forceinline__ void mma_tf32(float* c, const uint32_t* a, const uint32_t* b) {
    asm volatile(
        "mma.sync.aligned.m16n8k8.row.col.f32.tf32.tf32.f32 "
        "{%0,%1,%2,%3}, {%4,%5,%6,%7}, {%8,%9}, {%0,%1,%2,%3};"
        : "+f"(c[0]), "+f"(c[1]), "+f"(c[2]), "+f"(c[3])
        : "r"(a[0]), "r"(a[1]), "r"(a[2]), "r"(a[3]), "r"(b[0]), "r"(b[1]));
}

// ===========================================================================
// prep kernels
// ===========================================================================
__global__ void prep_convw(const float* __restrict__ cw, float* __restrict__ Wc) {
    int idx = blockIdx.x * 128 + threadIdx.x;
    int o = idx >> 9, rem = idx & 511, tap = rem >> 7, i = rem & 127;
    Wc[idx] = cw[o * 512 + i * 4 + tap];
}
__global__ void prep_lstmw(const float* __restrict__ wx, const float* __restrict__ wh,
                           float* __restrict__ Wl) {
    int idx = blockIdx.x * 128 + threadIdx.x;
    int o = idx >> 8, k = idx & 255;
    Wl[idx] = (k < 128) ? wx[o * 128 + k] : wh[o * 128 + (k - 128)];
}
__global__ void init_hc(const float* __restrict__ h0, const float* __restrict__ c0,
                        float* __restrict__ h, float* __restrict__ c) {
    int idx = blockIdx.x * 128 + threadIdx.x;
    int ch = idx >> 12, p = idx & 4095;
    h[p * 128 + ch] = h0[idx];
    c[p * 128 + ch] = c0[idx];
}

// NCHW -> NHWC transpose of x (output 33.5M floats -> g_Hid)
__global__ void transpose_x(const float* __restrict__ x, float* __restrict__ xt) {
    __shared__ float t[32][33];
    int bid = blockIdx.x;
    int tile = bid & 15, by = bid >> 4;
    int i0 = (tile >> 2) * 32, x0 = (tile & 3) * 32;
    int tx = threadIdx.x & 31, ty = threadIdx.x >> 5;
    const float* xin = x + (size_t)(by >> 7) * 2097152 + (size_t)(by & 127) * 128;
#pragma unroll
    for (int k = 0; k < 4; k++)
        t[ty + k * 8][tx] = xin[(size_t)(i0 + ty + k * 8) * 16384 + x0 + tx];
    __syncthreads();
    float* xout = xt + (size_t)by * 16384;
#pragma unroll
    for (int k = 0; k < 4; k++)
        xout[(size_t)(x0 + ty + k * 8) * 128 + i0 + tx] = t[tx][ty + k * 8];
}

// ===========================================================================
// generic mma.sync tf32 GEMM, double-buffered.
// MODE: 0 plain | 1 conv-im2col A | 2 lstm split A (Xn then A2=h)
// EPI: 0 bias | 1 bias+gelu | 2 bias+add-in-place |
//      6 bias + add-R + scatter-store window-reverse
// ===========================================================================
template<int MODE>
__device__ __forceinline__ const float* a_ptr(const float* A, const float* A2, int lda,
                                              int m, int k0) {
    if constexpr (MODE == 1) {
        int w = m >> 4, pl = m & 15;
        int b = w >> 8, yg = (w >> 4) & 15, xg = w & 15;
        int yl = pl >> 2, xl = pl & 3;
        int tap = k0 >> 7, ky = tap >> 1, kx = tap & 1;
        int Y = yg * 8 + yl * 2 + ky, XX = xg * 8 + xl * 2 + kx;
        return A + ((size_t)(b * 128 + Y) * 128 + XX) * 128 + (k0 & 127);
    } else if constexpr (MODE == 2) {
        return (k0 < 128) ? (A + (size_t)m * 128 + k0) : (A2 + (size_t)m * 128 + (k0 - 128));
    } else {
        return A + (size_t)m * lda + k0;
    }
}

__device__ __forceinline__ float gelu_exact(float v) {
    return 0.5f * v * (1.0f + erff(v * 0.70710678118654752f));
}

template<int MODE, int EPI>
__global__ void __launch_bounds__(256) mma_gemm(
        const float* __restrict__ A, const float* __restrict__ A2, int lda,
        const float* __restrict__ B, int ldb,
        const float* __restrict__ bias, const float* __restrict__ R,
        float* __restrict__ C, int ldc, int K) {
    constexpr int NT = 128;
    constexpr int MW = 2, MI = 4, NI = 4;   // warp tile 64x32
    constexpr int BUF = (128 + NT) * 36;

    extern __shared__ __align__(16) uint32_t sm[];
    __shared__ float sbias[NT];

    const int tid = threadIdx.x, wid = tid >> 5, lane = tid & 31;
    const int bm = blockIdx.y * 128, bn = blockIdx.x * NT;
    const int wm0 = (wid & (MW - 1)) * 64;
    const int wn0 = (wid / MW) * 32;
    const int srow = tid >> 3, scol = tid & 7;

    if (EPI == 0 || EPI == 1 || EPI == 2 || EPI == 6) {
        for (int i = tid; i < NT; i += 256) sbias[i] = bias[bn + i];
    }

    float acc[MI][NI][4];
#pragma unroll
    for (int mi = 0; mi < MI; mi++)
#pragma unroll
        for (int ni = 0; ni < NI; ni++)
#pragma unroll
            for (int q = 0; q < 4; q++) acc[mi][ni][q] = 0.f;

    float4 aReg[4];
    float4 bReg[4];

    auto ldg = [&](int k0) {
#pragma unroll
        for (int it = 0; it < 4; it++)
            aReg[it] = ((const float4*)a_ptr<MODE>(A, A2, lda, bm + it * 32 + srow, k0))[scol];
#pragma unroll
        for (int it = 0; it < 4; it++)
            bReg[it] = ((const float4*)(B + (size_t)(bn + it * 32 + srow) * ldb + k0))[scol];
    };
    auto sts = [&](int buf) {
        uint32_t* base = sm + buf * BUF;
#pragma unroll
        for (int it = 0; it < 4; it++) {
            float4 v = aReg[it];
            uint4 u = make_uint4(f2tf32(v.x), f2tf32(v.y), f2tf32(v.z), f2tf32(v.w));
            *(uint4*)&base[(it * 32 + srow) * 36 + scol * 4] = u;
        }
        uint32_t* bb = base + 128 * 36;
#pragma unroll
        for (int it = 0; it < 4; it++) {
            float4 v = bReg[it];
            uint4 u = make_uint4(f2tf32(v.x), f2tf32(v.y), f2tf32(v.z), f2tf32(v.w));
            *(uint4*)&bb[(it * 32 + srow) * 36 + scol * 4] = u;
        }
    };
    auto compute = [&](int buf) {
        const uint32_t* Ab = sm + buf * BUF;
        const uint32_t* Bb = Ab + 128 * 36;
#pragma unroll
        for (int ks = 0; ks < 4; ks++) {
            int kq = ks * 8 + (lane & 3);
            uint32_t afr[MI][4];
#pragma unroll
            for (int mi = 0; mi < MI; mi++) {
                int r = wm0 + mi * 16 + (lane >> 2);
                afr[mi][0] = Ab[r * 36 + kq];
                afr[mi][1] = Ab[(r + 8) * 36 + kq];
                afr[mi][2] = Ab[r * 36 + kq + 4];
                afr[mi][3] = Ab[(r + 8) * 36 + kq + 4];
            }
            uint32_t bfr[NI][2];
#pragma unroll
            for (int ni = 0; ni < NI; ni++) {
                int n = wn0 + ni * 8 + (lane >> 2);
                bfr[ni][0] = Bb[n * 36 + kq];
                bfr[ni][1] = Bb[n * 36 + kq + 4];
            }
#pragma unroll
            for (int mi = 0; mi < MI; mi++)
#pragma unroll
                for (int ni = 0; ni < NI; ni++)
                    mma_tf32(acc[mi][ni], afr[mi], bfr[ni]);
        }
    };

    const int NCH = K >> 5;
    ldg(0);
    sts(0);
    int cur = 0;
    for (int ch = 0; ch < NCH; ch++) {
        __syncthreads();
        if (ch + 1 < NCH) ldg((ch + 1) << 5);
        compute(cur);
        if (ch + 1 < NCH) sts(cur ^ 1);
        cur ^= 1;
    }

    // ---- epilogue ----
#pragma unroll
    for (int mi = 0; mi < MI; mi++) {
#pragma unroll
        for (int ni = 0; ni < NI; ni++) {
#pragma unroll
            for (int half = 0; half < 2; half++) {
                int row = bm + wm0 + mi * 16 + (lane >> 2) + half * 8;
                int cl = wn0 + ni * 8 + 2 * (lane & 3);
                float f0 = acc[mi][ni][half * 2 + 0];
                float f1 = acc[mi][ni][half * 2 + 1];
                if constexpr (EPI == 0 || EPI == 2 || EPI == 6) { f0 += sbias[cl]; f1 += sbias[cl + 1]; }
                else if constexpr (EPI == 1) { f0 = gelu_exact(f0 + sbias[cl]); f1 = gelu_exact(f1 + sbias[cl + 1]); }
                float* cp;
                if constexpr (EPI == 6) {
                    int n_ = row >> 12, w_ = (row >> 4) & 255, pl = row & 15;
                    int p = ((w_ >> 4) * 4 + (pl >> 2)) * 64 + (w_ & 15) * 4 + (pl & 3);
                    cp = C + ((size_t)n_ * 4096 + p) * 128 + bn + cl;
                } else {
                    cp = C + (size_t)row * ldc + bn + cl;
                }
                float2 v = make_float2(f0, f1);
                if constexpr (EPI == 2) {
                    float2 o = *(float2*)cp;
                    v.x += o.x; v.y += o.y;
                }
                if constexpr (EPI == 6) {
                    float2 o = *(const float2*)(R + (size_t)row * ldc + bn + cl);
                    v.x += o.x; v.y += o.y;
                }
                *(float2*)cp = v;
            }
        }
    }
}

// ===========================================================================
// attention 1: per window (16 tokens, 2 heads, hd=64). X += attn(V)
// ===========================================================================
__global__ void attn1_kernel(const float* __restrict__ QKV, float* __restrict__ X) {
    __shared__ float q[16][384];
    __shared__ float s[2][16][16];
    int w = blockIdx.x, tid = threadIdx.x;
    size_t base = (size_t)w * 16 * 384;
    for (int i = tid; i < 16 * 384; i += 128) q[i / 384][i % 384] = QKV[base + i];
    __syncthreads();
    for (int idx = tid; idx < 512; idx += 128) {
        int h = idx >> 8, t1 = (idx >> 4) & 15, t2 = idx & 15;
        const float* qp = &q[t1][h * 64];
        const float* kp = &q[t2][128 + h * 64];
        float a = 0.f;
#pragma unroll
        for (int c = 0; c < 64; c++) a = fmaf(qp[c], kp[c], a);
        s[h][t1][t2] = a * 0.08838834764831843f;
    }
    __syncthreads();
    if (tid < 32) {
        int h = tid >> 4, t1 = tid & 15;
        float m = -1e30f;
#pragma unroll
        for (int j = 0; j < 16; j++) m = fmaxf(m, s[h][t1][j]);
        float sum = 0.f;
#pragma unroll
        for (int j = 0; j < 16; j++) { float e = expf(s[h][t1][j] - m); s[h][t1][j] = e; sum += e; }
        float inv = 1.f / sum;
#pragma unroll
        for (int j = 0; j < 16; j++) s[h][t1][j] *= inv;
    }
    __syncthreads();
    for (int idx = tid; idx < 2048; idx += 128) {
        int t1 = idx >> 7, ch = idx & 127, h = ch >> 6;
        float a = 0.f;
#pragma unroll
        for (int j = 0; j < 16; j++) a = fmaf(s[h][t1][j], q[j][256 + ch], a);
        X[(size_t)(w * 16 + t1) * 128 + ch] += a;
    }
}

// ===========================================================================
// attention 2 FUSED (flash-style, tensor cores): X += softmax(QK^T/sqrt(c)) V
// grid (2 query-halves, 512 (b,l,head)); 256 threads / 8 warps.
// Warp owns 16 query rows -> all row stats warp-local (quad shfl).
// K [256][68] + V^T [64][260] + P/Q pane [128][68] in smem (tf32-rounded).
// ===========================================================================
__global__ void __launch_bounds__(256, 1) attn2_fused(
        const float* __restrict__ QKV, float* __restrict__ X) {
    extern __shared__ __align__(16) float smf[];
    float* Ks = smf;                  // [256][68]
    float* Vt = smf + 256 * 68;       // [64][260]
    float* Ps = Vt + 64 * 260;        // [128][68] (Q staging, then per-warp P)

    const int tid = threadIdx.x, wid = tid >> 5, lane = tid & 31;
    const int g0 = blockIdx.x * 128;
    const int blh = blockIdx.y;
    const int b = blh >> 5, l = (blh >> 1) & 15, h = blh & 1;
    const int qoff = h * 64, koff = 128 + h * 64, voff = 256 + h * 64;

    // ---- stage Q (into Ps), K, V^T ----
    for (int i = tid * 4; i < 128 * 64; i += 1024) {
        int g = i >> 6, c = i & 63;
        size_t t = (size_t)(b * 256 + g0 + g) * 16 + l;
        float4 v = *(const float4*)&QKV[t * 384 + qoff + c];
        uint4 u = make_uint4(f2tf32(v.x), f2tf32(v.y), f2tf32(v.z), f2tf32(v.w));
        *(uint4*)&Ps[g * 68 + c] = u;
    }
    for (int i = tid * 4; i < 256 * 64; i += 1024) {
        int g = i >> 6, c = i & 63;
        size_t t = (size_t)(b * 256 + g) * 16 + l;
        float4 v = *(const float4*)&QKV[t * 384 + koff + c];
        uint4 u = make_uint4(f2tf32(v.x), f2tf32(v.y), f2tf32(v.z), f2tf32(v.w));
        *(uint4*)&Ks[g * 68 + c] = u;
    }
    for (int i = tid; i < 256 * 16; i += 256) {
        int g = i >> 4, c4 = (i & 15) * 4;
        size_t t = (size_t)(b * 256 + g) * 16 + l;
        float4 v = *(const float4*)&QKV[t * 384 + voff + c4];
        Vt[(c4 + 0) * 260 + g] = __uint_as_float(f2tf32(v.x));
        Vt[(c4 + 1) * 260 + g] = __uint_as_float(f2tf32(v.y));
        Vt[(c4 + 2) * 260 + g] = __uint_as_float(f2tf32(v.z));
        Vt[(c4 + 3) * 260 + g] = __uint_as_float(f2tf32(v.w));
    }
    __syncthreads();

    // ---- Q fragments (persistent; warp-private rows) ----
    const int r0 = wid * 16 + (lane >> 2);
    uint32_t qfr[8][4];
#pragma unroll
    for (int kt = 0; kt < 8; kt++) {
        int kq = kt * 8 + (lane & 3);
        qfr[kt][0] = __float_as_uint(Ps[r0 * 68 + kq]);
        qfr[kt][1] = __float_as_uint(Ps[(r0 + 8) * 68 + kq]);
        qfr[kt][2] = __float_as_uint(Ps[r0 * 68 + kq + 4]);
        qfr[kt][3] = __float_as_uint(Ps[(r0 + 8) * 68 + kq + 4]);
    }
    // (no sync needed: each warp reads/writes only its own Ps rows from here)

    float accO[8][4];
#pragma unroll
    for (int ni = 0; ni < 8; ni++)
#pragma unroll
        for (int q = 0; q < 4; q++) accO[ni][q] = 0.f;
    float m0 = -1e30f, m1 = -1e30f, l0 = 0.f, l1 = 0.f;

    for (int it = 0; it < 4; it++) {
        const int j0 = it * 64;
        // ---- S = Q @ K_chunk^T ----
        float accS[8][4];
#pragma unroll
        for (int ni = 0; ni < 8; ni++)
#pragma unroll
            for (int q = 0; q < 4; q++) accS[ni][q] = 0.f;
#pragma unroll
        for (int kt = 0; kt < 8; kt++) {
            int kq = kt * 8 + (lane & 3);
#pragma unroll
            for (int ni = 0; ni < 8; ni++) {
                int n = j0 + ni * 8 + (lane >> 2);
                uint32_t bfr[2];
                bfr[0] = __float_as_uint(Ks[n * 68 + kq]);
                bfr[1] = __float_as_uint(Ks[n * 68 + kq + 4]);
                mma_tf32(accS[ni], qfr[kt], bfr);
            }
        }
        // ---- online softmax (rows r0, r0+8; quad-local) ----
        float rm0 = -1e30f, rm1 = -1e30f;
#pragma unroll
        for (int ni = 0; ni < 8; ni++) {
#pragma unroll
            for (int q = 0; q < 4; q++) accS[ni][q] *= 0.08838834764831843f;
            rm0 = fmaxf(rm0, fmaxf(accS[ni][0], accS[ni][1]));
            rm1 = fmaxf(rm1, fmaxf(accS[ni][2], accS[ni][3]));
        }
#pragma unroll
        for (int o = 1; o < 4; o <<= 1) {
            rm0 = fmaxf(rm0, __shfl_xor_sync(0xffffffffu, rm0, o));
            rm1 = fmaxf(rm1, __shfl_xor_sync(0xffffffffu, rm1, o));
        }
        float m0n = fmaxf(m0, rm0), m1n = fmaxf(m1, rm1);
        float corr0 = expf(m0 - m0n), corr1 = expf(m1 - m1n);
        float s0 = 0.f, s1 = 0.f;
#pragma unroll
        for (int ni = 0; ni < 8; ni++) {
            float p0 = expf(accS[ni][0] - m0n);
            float p1 = expf(accS[ni][1] - m0n);
            float p2 = expf(accS[ni][2] - m1n);
            float p3 = expf(accS[ni][3] - m1n);
            s0 += p0 + p1; s1 += p2 + p3;
            int cl = ni * 8 + 2 * (lane & 3);
            Ps[r0 * 68 + cl]       = __uint_as_float(f2tf32(p0));
            Ps[r0 * 68 + cl + 1]   = __uint_as_float(f2tf32(p1));
            Ps[(r0 + 8) * 68 + cl]     = __uint_as_float(f2tf32(p2));
            Ps[(r0 + 8) * 68 + cl + 1] = __uint_as_float(f2tf32(p3));
        }
#pragma unroll
        for (int o = 1; o < 4; o <<= 1) {
            s0 += __shfl_xor_sync(0xffffffffu, s0, o);
            s1 += __shfl_xor_sync(0xffffffffu, s1, o);
        }
        l0 = l0 * corr0 + s0; l1 = l1 * corr1 + s1;
        m0 = m0n; m1 = m1n;
#pragma unroll
        for (int ni = 0; ni < 8; ni++) {
            accO[ni][0] *= corr0; accO[ni][1] *= corr0;
            accO[ni][2] *= corr1; accO[ni][3] *= corr1;
        }
        __syncwarp();
        // ---- O += P_chunk @ V_chunk ----
#pragma unroll
        for (int kt = 0; kt < 8; kt++) {
            int kq = kt * 8 + (lane & 3);
            uint32_t pfr[4];
            pfr[0] = __float_as_uint(Ps[r0 * 68 + kq]);
            pfr[1] = __float_as_uint(Ps[(r0 + 8) * 68 + kq]);
            pfr[2] = __float_as_uint(Ps[r0 * 68 + kq + 4]);
            pfr[3] = __float_as_uint(Ps[(r0 + 8) * 68 + kq + 4]);
#pragma unroll
            for (int ni = 0; ni < 8; ni++) {
                int n = ni * 8 + (lane >> 2);
                uint32_t bfr[2];
                bfr[0] = __float_as_uint(Vt[n * 260 + j0 + kq]);
                bfr[1] = __float_as_uint(Vt[n * 260 + j0 + kq + 4]);
                mma_tf32(accO[ni], pfr, bfr);
            }
        }
        __syncwarp();
    }

    // ---- write X += O / l ----
    float rinv0 = 1.f / l0, rinv1 = 1.f / l1;
#pragma unroll
    for (int half = 0; half < 2; half++) {
        int g = g0 + r0 + half * 8;
        size_t t = (size_t)(b * 256 + g) * 16 + l;
        float* xp = &g_X[t * 128 + h * 64];
        float rinv = half ? rinv1 : rinv0;
#pragma unroll
        for (int ni = 0; ni < 8; ni++) {
            int cl = ni * 8 + 2 * (lane & 3);
            float2 o = *(float2*)&xp[cl];
            o.x += accO[ni][half * 2 + 0] * rinv;
            o.y += accO[ni][half * 2 + 1] * rinv;
            *(float2*)&xp[cl] = o;
        }
    }
    (void)X;
}

// ===========================================================================
// LSTM pointwise
// ===========================================================================
__device__ __forceinline__ float softmax128(float v, float* red) {
    const unsigned FULL = 0xffffffffu;
    float m = v;
#pragma unroll
    for (int o = 16; o; o >>= 1) m = fmaxf(m, __shfl_xor_sync(FULL, m, o));
    if ((threadIdx.x & 31) == 0) red[threadIdx.x >> 5] = m;
    __syncthreads();
    m = fmaxf(fmaxf(red[0], red[1]), fmaxf(red[2], red[3]));
    __syncthreads();
    float e = expf(v - m), s = e;
#pragma unroll
    for (int o = 16; o; o >>= 1) s += __shfl_xor_sync(FULL, s, o);
    if ((threadIdx.x & 31) == 0) red[threadIdx.x >> 5] = s;
    __syncthreads();
    s = red[0] + red[1] + red[2] + red[3];
    __syncthreads();
    return e / s;
}

__global__ void lstm_point(const float* __restrict__ gates, float* __restrict__ h,
                           float* __restrict__ cst, float* __restrict__ out, int n) {
    __shared__ float red[4];
    int p = blockIdx.x, tid = threadIdx.x;
    float f  = gates[p * 512 + tid];
    float ig = gates[p * 512 + 128 + tid];
    float s  = gates[p * 512 + 256 + tid];
    float o  = gates[p * 512 + 384 + tid];
    f  = softmax128(f,  red);
    ig = softmax128(ig, red);
    o  = softmax128(o,  red);
    float cc = cst[p * 128 + tid];
    float cn = f * cc + ig * tanhf(s);
    float hn = o * tanhf(cn);
    cst[p * 128 + tid] = cn;
    h[p * 128 + tid]   = hn;
    out[((size_t)(n * 128 + tid)) * 4096 + p] = hn;
    if (n == 15) {
        out[((size_t)(16 * 128 + tid)) * 4096 + p] = hn;
        out[((size_t)(17 * 128 + tid)) * 4096 + p] = cn;
    }
}

// ===========================================================================
extern "C" void kernel_launch(void* const* d_in, const int* in_sizes, int n_in,
                              void* d_out, int out_size) {
    const float* x       = (const float*)d_in[0];
    const float* h0      = (const float*)d_in[1];
    const float* c0      = (const float*)d_in[2];
    const float* conv_w  = (const float*)d_in[3];
    const float* conv_b  = (const float*)d_in[4];
    const float* qkv1_w  = (const float*)d_in[5];
    const float* qkv1_b  = (const float*)d_in[6];
    const float* mlp1_w1 = (const float*)d_in[7];
    const float* mlp1_b1 = (const float*)d_in[8];
    const float* mlp1_w2 = (const float*)d_in[9];
    const float* mlp1_b2 = (const float*)d_in[10];
    const float* qkv2_w  = (const float*)d_in[11];
    const float* qkv2_b  = (const float*)d_in[12];
    const float* mlp2_w1 = (const float*)d_in[13];
    const float* mlp2_b1 = (const float*)d_in[14];
    const float* mlp2_w2 = (const float*)d_in[15];
    const float* mlp2_b2 = (const float*)d_in[16];
    const float* lstm_wx = (const float*)d_in[17];
    const float* lstm_wh = (const float*)d_in[18];
    const float* lstm_bh = (const float*)d_in[19];
    float* out = (float*)d_out;
    (void)in_sizes; (void)n_in; (void)out_size;

    float *X, *QKV, *Hid, *Xr, *h, *c, *gates, *Wc, *Wl;
    cudaGetSymbolAddress((void**)&X, g_X);
    cudaGetSymbolAddress((void**)&QKV, g_QKV);
    cudaGetSymbolAddress((void**)&Hid, g_Hid);
    cudaGetSymbolAddress((void**)&Xr, g_Xr);
    cudaGetSymbolAddress((void**)&h, g_h);
    cudaGetSymbolAddress((void**)&c, g_c);
    cudaGetSymbolAddress((void**)&gates, g_gates);
    cudaGetSymbolAddress((void**)&Wc, g_Wc);
    cudaGetSymbolAddress((void**)&Wl, g_Wl);

    const int SM128 = 2 * (128 + 128) * 36 * 4;                    // 73728
    const int SMATT = (256 * 68 + 64 * 260 + 128 * 68) * 4;       // 171008
    cudaFuncSetAttribute((const void*)mma_gemm<1, 0>, cudaFuncAttributeMaxDynamicSharedMemorySize, SM128);
    cudaFuncSetAttribute((const void*)mma_gemm<0, 0>, cudaFuncAttributeMaxDynamicSharedMemorySize, SM128);
    cudaFuncSetAttribute((const void*)mma_gemm<0, 1>, cudaFuncAttributeMaxDynamicSharedMemorySize, SM128);
    cudaFuncSetAttribute((const void*)mma_gemm<0, 2>, cudaFuncAttributeMaxDynamicSharedMemorySize, SM128);
    cudaFuncSetAttribute((const void*)mma_gemm<0, 6>, cudaFuncAttributeMaxDynamicSharedMemorySize, SM128);
    cudaFuncSetAttribute((const void*)mma_gemm<2, 0>, cudaFuncAttributeMaxDynamicSharedMemorySize, SM128);
    cudaFuncSetAttribute((const void*)attn2_fused, cudaFuncAttributeMaxDynamicSharedMemorySize, SMATT);

    prep_convw<<<512, 128>>>(conv_w, Wc);
    prep_lstmw<<<1024, 128>>>(lstm_wx, lstm_wh, Wl);
    init_hc<<<4096, 128>>>(h0, c0, h, c);
    transpose_x<<<32768, 256>>>(x, Hid);

    // conv as implicit-im2col GEMM
    mma_gemm<1, 0><<<dim3(1, 512), 256, SM128>>>(Hid, nullptr, 0, Wc, 512, conv_b, nullptr, X, 128, 512);

    // LocalMSA
    mma_gemm<0, 0><<<dim3(3, 512), 256, SM128>>>(X, nullptr, 128, qkv1_w, 128, qkv1_b, nullptr, QKV, 384, 128);
    attn1_kernel<<<NWIN, 128>>>(QKV, X);
    // MLP1
    mma_gemm<0, 1><<<dim3(4, 512), 256, SM128>>>(X, nullptr, 128, mlp1_w1, 128, mlp1_b1, nullptr, Hid, 512, 128);
    mma_gemm<0, 2><<<dim3(1, 512), 256, SM128>>>(Hid, nullptr, 512, mlp1_w2, 512, mlp1_b2, nullptr, X, 128, 512);

    // DilatedMSA — single fused flash-attention kernel
    mma_gemm<0, 0><<<dim3(3, 512), 256, SM128>>>(X, nullptr, 128, qkv2_w, 128, qkv2_b, nullptr, QKV, 384, 128);
    attn2_fused<<<dim3(2, 512), 256, SMATT>>>(QKV, X);
    // MLP2 (second GEMM fuses residual + window-reverse scatter into Xr)
    mma_gemm<0, 1><<<dim3(4, 512), 256, SM128>>>(X, nullptr, 128, mlp2_w1, 128, mlp2_b1, nullptr, Hid, 512, 128);
    mma_gemm<0, 6><<<dim3(1, 512), 256, SM128>>>(Hid, nullptr, 512, mlp2_w2, 512, mlp2_b2, X, Xr, 128, 512);

    // ConvLSTM scan (R8 structure)
    for (int n = 0; n < 16; n++) {
        mma_gemm<2, 0><<<dim3(4, 32), 256, SM128>>>(
            Xr + (size_t)n * NPIX * 128, h, 128, Wl, 256, lstm_bh, nullptr, gates, 512, 256);
        lstm_point<<<NPIX, 128>>>(gates, h, c, out, n);
    }
}